// round 5
// baseline (speedup 1.0000x reference)
#include <cuda_runtime.h>

// ---------------- problem constants ----------------
#define NN0 540672
#define NN1 33792
#define NN2 3072
#define NN3 512
#define EE0 506880
#define EE1 30720
#define EE2 2560
#define FF0 256
#define HH  1024
#define CC  47

// ---------------- device scratch (no allocations allowed) ----------------
__device__ float g_mean[NN1 * FF0];      // 8.65M floats; reused by later layers (they need <=3.2M)
__device__ float g_h1[(size_t)NN1 * HH]; // 34.6M floats
__device__ float g_h2[(size_t)NN2 * HH]; // 3.1M floats
__device__ int   g_deg[NN1];
__device__ int   g_off[NN1];
__device__ int   g_cur[NN1];
__device__ int   g_esrc[EE0];

// ---------------- CSR build ----------------
__global__ void zero_deg_k(int n) {
    int i = blockIdx.x * blockDim.x + threadIdx.x;
    if (i < n) g_deg[i] = 0;
}

__global__ void count_deg_k(const int* __restrict__ dst, int E) {
    int i = blockIdx.x * blockDim.x + threadIdx.x;
    if (i < E) atomicAdd(&g_deg[dst[i]], 1);
}

// single-block exclusive scan of g_deg -> g_off (and copy to g_cur)
__global__ void exscan_k(int n) {
    __shared__ int buf[1024];
    int base = 0;
    for (int start = 0; start < n; start += 1024) {
        int i = start + (int)threadIdx.x;
        int v = (i < n) ? g_deg[i] : 0;
        __syncthreads();                 // protect buf from previous-chunk readers
        buf[threadIdx.x] = v;
        __syncthreads();
        #pragma unroll
        for (int off = 1; off < 1024; off <<= 1) {
            int t = (threadIdx.x >= (unsigned)off) ? buf[threadIdx.x - off] : 0;
            __syncthreads();
            buf[threadIdx.x] += t;
            __syncthreads();
        }
        int incl  = buf[threadIdx.x];
        int total = buf[1023];
        if (i < n) {
            int ex = base + incl - v;
            g_off[i] = ex;
            g_cur[i] = ex;
        }
        base += total;
    }
}

__global__ void scatter_k(const int* __restrict__ src, const int* __restrict__ dst, int E) {
    int i = blockIdx.x * blockDim.x + threadIdx.x;
    if (i < E) {
        int p = atomicAdd(&g_cur[dst[i]], 1);
        g_esrc[p] = src[i];
    }
}

// ---------------- segment mean (one block per dst node) ----------------
template <int F>
__global__ void aggregate_k(const float* __restrict__ feat, float* __restrict__ out) {
    int v = blockIdx.x;
    int t = threadIdx.x;             // F/4 threads, one float4 lane each
    int o = g_off[v];
    int d = g_deg[v];
    float4 acc = make_float4(0.f, 0.f, 0.f, 0.f);
    for (int j = 0; j < d; j++) {
        int s = g_esrc[o + j];
        float4 x = *reinterpret_cast<const float4*>(&feat[(size_t)s * F + t * 4]);
        acc.x += x.x; acc.y += x.y; acc.z += x.z; acc.w += x.w;
    }
    float inv = 1.0f / (float)max(d, 1);
    acc.x *= inv; acc.y *= inv; acc.z *= inv; acc.w *= inv;
    *reinterpret_cast<float4*>(&out[(size_t)v * F + t * 4]) = acc;
}

// ---------------- dual-input GEMM: C = act(A1@B1 + A2@B2 + bias) ----------------
// BM=BN=128, BK=8, 8x8 microtile, 256 threads. Requires M%128==0, N%128==0, K%8==0.
template <bool RELU>
__global__ __launch_bounds__(256, 2)
void gemm_dual_k(const float* __restrict__ A1, const float* __restrict__ A2,
                 const float* __restrict__ B1, const float* __restrict__ B2,
                 const float* __restrict__ bias, float* __restrict__ C,
                 int M, int N, int K) {
    constexpr int BM = 128, BN = 128, BK = 8, TM = 8, TN = 8;
    __shared__ float As[BK][BM];
    __shared__ float Bs[BK][BN];
    int tid = threadIdx.x;
    int bm = blockIdx.y * BM;
    int bn = blockIdx.x * BN;
    int tr = (tid / 16) * TM;
    int tc = (tid % 16) * TN;
    int arow = tid / 2;            // 0..127
    int acol = (tid & 1) * 4;      // 0 or 4
    int brow = tid / 32;           // 0..7
    int bcol = (tid & 31) * 4;     // 0..124

    float acc[TM][TN];
    #pragma unroll
    for (int i = 0; i < TM; i++)
        #pragma unroll
        for (int j = 0; j < TN; j++) acc[i][j] = 0.f;

    #pragma unroll 1
    for (int pass = 0; pass < 2; pass++) {
        const float* __restrict__ A = pass ? A2 : A1;
        const float* __restrict__ B = pass ? B2 : B1;
        #pragma unroll 1
        for (int k0 = 0; k0 < K; k0 += BK) {
            float4 av = *reinterpret_cast<const float4*>(&A[(size_t)(bm + arow) * K + k0 + acol]);
            As[acol + 0][arow] = av.x;
            As[acol + 1][arow] = av.y;
            As[acol + 2][arow] = av.z;
            As[acol + 3][arow] = av.w;
            *reinterpret_cast<float4*>(&Bs[brow][bcol]) =
                *reinterpret_cast<const float4*>(&B[(size_t)(k0 + brow) * N + bn + bcol]);
            __syncthreads();
            #pragma unroll
            for (int k = 0; k < BK; k++) {
                float ra[TM], rb[TN];
                float4 a0 = *reinterpret_cast<float4*>(&As[k][tr]);
                float4 a1 = *reinterpret_cast<float4*>(&As[k][tr + 4]);
                ra[0]=a0.x; ra[1]=a0.y; ra[2]=a0.z; ra[3]=a0.w;
                ra[4]=a1.x; ra[5]=a1.y; ra[6]=a1.z; ra[7]=a1.w;
                float4 b0 = *reinterpret_cast<float4*>(&Bs[k][tc]);
                float4 b1 = *reinterpret_cast<float4*>(&Bs[k][tc + 4]);
                rb[0]=b0.x; rb[1]=b0.y; rb[2]=b0.z; rb[3]=b0.w;
                rb[4]=b1.x; rb[5]=b1.y; rb[6]=b1.z; rb[7]=b1.w;
                #pragma unroll
                for (int i = 0; i < TM; i++)
                    #pragma unroll
                    for (int j = 0; j < TN; j++)
                        acc[i][j] += ra[i] * rb[j];
            }
            __syncthreads();
        }
    }

    #pragma unroll
    for (int i = 0; i < TM; i++) {
        size_t row = (size_t)(bm + tr + i);
        #pragma unroll
        for (int jj = 0; jj < TN; jj += 4) {
            float4 o;
            o.x = acc[i][jj + 0] + bias[bn + tc + jj + 0];
            o.y = acc[i][jj + 1] + bias[bn + tc + jj + 1];
            o.z = acc[i][jj + 2] + bias[bn + tc + jj + 2];
            o.w = acc[i][jj + 3] + bias[bn + tc + jj + 3];
            if (RELU) {
                o.x = fmaxf(o.x, 0.f); o.y = fmaxf(o.y, 0.f);
                o.z = fmaxf(o.z, 0.f); o.w = fmaxf(o.w, 0.f);
            }
            *reinterpret_cast<float4*>(&C[row * N + bn + tc + jj]) = o;
        }
    }
}

// ---------------- small final GEMM (N=47): one block per output row ----------------
__global__ void gemm_small_k(const float* __restrict__ A1, const float* __restrict__ A2,
                             const float* __restrict__ B1, const float* __restrict__ B2,
                             const float* __restrict__ bias, float* __restrict__ C,
                             int K, int N) {
    __shared__ float a1[HH];
    __shared__ float a2[HH];
    int m = blockIdx.x;
    for (int i = threadIdx.x; i < K; i += blockDim.x) {
        a1[i] = A1[(size_t)m * K + i];
        a2[i] = A2[(size_t)m * K + i];
    }
    __syncthreads();
    for (int c = threadIdx.x; c < N; c += blockDim.x) {
        float s = bias[c];
        #pragma unroll 8
        for (int k = 0; k < K; k++)
            s += a1[k] * B1[(size_t)k * N + c] + a2[k] * B2[(size_t)k * N + c];
        C[(size_t)m * N + c] = s;
    }
}

// ---------------- launch ----------------
extern "C" void kernel_launch(void* const* d_in, const int* in_sizes, int n_in,
                              void* d_out, int out_size) {
    const float* x   = (const float*)d_in[0];
    const int* src0  = (const int*)d_in[1];
    const int* dst0  = (const int*)d_in[2];
    const int* src1  = (const int*)d_in[3];
    const int* dst1  = (const int*)d_in[4];
    const int* src2  = (const int*)d_in[5];
    const int* dst2  = (const int*)d_in[6];
    const float* Ws0 = (const float*)d_in[7];
    const float* Wn0 = (const float*)d_in[8];
    const float* b0  = (const float*)d_in[9];
    const float* Ws1 = (const float*)d_in[10];
    const float* Wn1 = (const float*)d_in[11];
    const float* b1  = (const float*)d_in[12];
    const float* Ws2 = (const float*)d_in[13];
    const float* Wn2 = (const float*)d_in[14];
    const float* b2  = (const float*)d_in[15];
    float* out = (float*)d_out;

    float *mean_p, *h1_p, *h2_p;
    cudaGetSymbolAddress((void**)&mean_p, g_mean);
    cudaGetSymbolAddress((void**)&h1_p, g_h1);
    cudaGetSymbolAddress((void**)&h2_p, g_h2);

    // ---- Layer 0: x[N0,256] -> h1[N1,1024], ReLU ----
    zero_deg_k<<<(NN1 + 255) / 256, 256>>>(NN1);
    count_deg_k<<<(EE0 + 255) / 256, 256>>>(dst0, EE0);
    exscan_k<<<1, 1024>>>(NN1);
    scatter_k<<<(EE0 + 255) / 256, 256>>>(src0, dst0, EE0);
    aggregate_k<FF0><<<NN1, FF0 / 4>>>(x, mean_p);
    {
        dim3 grid(HH / 128, NN1 / 128);
        gemm_dual_k<true><<<grid, 256>>>(x, mean_p, Ws0, Wn0, b0, h1_p, NN1, HH, FF0);
    }

    // ---- Layer 1: h1[N1,1024] -> h2[N2,1024], ReLU ----
    zero_deg_k<<<(NN2 + 255) / 256, 256>>>(NN2);
    count_deg_k<<<(EE1 + 255) / 256, 256>>>(dst1, EE1);
    exscan_k<<<1, 1024>>>(NN2);
    scatter_k<<<(EE1 + 255) / 256, 256>>>(src1, dst1, EE1);
    aggregate_k<HH><<<NN2, HH / 4>>>(h1_p, mean_p);
    {
        dim3 grid(HH / 128, NN2 / 128);
        gemm_dual_k<true><<<grid, 256>>>(h1_p, mean_p, Ws1, Wn1, b1, h2_p, NN2, HH, HH);
    }

    // ---- Layer 2: h2[N2,1024] -> out[N3,47], no activation ----
    zero_deg_k<<<(NN3 + 255) / 256, 256>>>(NN3);
    count_deg_k<<<(EE2 + 255) / 256, 256>>>(dst2, EE2);
    exscan_k<<<1, 1024>>>(NN3);
    scatter_k<<<(EE2 + 255) / 256, 256>>>(src2, dst2, EE2);
    aggregate_k<HH><<<NN3, HH / 4>>>(h2_p, mean_p);
    gemm_small_k<<<NN3, 128>>>(h2_p, mean_p, Ws2, Wn2, b2, out, HH, CC);
}

// round 7
// speedup vs baseline: 2.0032x; 2.0032x over previous
#include <cuda_runtime.h>
#include <cstdint>

// ---------------- problem constants ----------------
#define NN0 540672
#define NN1 33792
#define NN2 3072
#define NN3 512
#define EE0 506880
#define EE1 30720
#define EE2 2560
#define FF0 256
#define HH  1024
#define CC  47

// ---------------- device scratch (no allocations allowed) ----------------
__device__ float g_mean[NN1 * FF0];      // 8.65M floats; layer1/2 need <=3.2M
__device__ float g_h1[(size_t)NN1 * HH]; // 34.6M floats
__device__ float g_h2[(size_t)NN2 * HH]; // 3.1M floats
__device__ int   g_deg[NN1];
__device__ int   g_off[NN1];
__device__ int   g_cur[NN1];
__device__ int   g_esrc[EE0];
// transposed + tf32-rounded weights, [N][K] K-major
__device__ float g_W0t[2 * HH * FF0];    // 2 x [1024][256]
__device__ float g_W1t[2 * HH * HH];     // 2 x [1024][1024]

// ---------------- helpers ----------------
__device__ __forceinline__ uint32_t smem_to_u32(const void* p) {
    uint32_t a;
    asm("{ .reg .u64 t; cvta.to.shared.u64 t, %1; cvt.u32.u64 %0, t; }" : "=r"(a) : "l"(p));
    return a;
}
__device__ __forceinline__ float to_tf32(float x) {
    uint32_t u = __float_as_uint(x), r;
    asm("cvt.rna.tf32.f32 %0, %1;" : "=r"(r) : "r"(u));
    return __uint_as_float(r);
}
__device__ __forceinline__ void cp_async16(uint32_t saddr, const void* gaddr) {
    asm volatile("cp.async.ca.shared.global [%0], [%1], 16;" :: "r"(saddr), "l"(gaddr) : "memory");
}
__device__ __forceinline__ void cp_commit() {
    asm volatile("cp.async.commit_group;" ::: "memory");
}
template <int N>
__device__ __forceinline__ void cp_wait() {
    asm volatile("cp.async.wait_group %0;" :: "n"(N) : "memory");
}
__device__ __forceinline__ void mma_tf32(float* c, const uint32_t* a, const uint32_t* b) {
    asm volatile(
        "mma.sync.aligned.m16n8k8.row.col.f32.tf32.tf32.f32 "
        "{%0,%1,%2,%3}, {%4,%5,%6,%7}, {%8,%9}, {%0,%1,%2,%3};"
        : "+f"(c[0]), "+f"(c[1]), "+f"(c[2]), "+f"(c[3])
        : "r"(a[0]), "r"(a[1]), "r"(a[2]), "r"(a[3]), "r"(b[0]), "r"(b[1]));
}

// ---------------- CSR build ----------------
__global__ void zero_deg_k(int n) {
    int i = blockIdx.x * blockDim.x + threadIdx.x;
    if (i < n) g_deg[i] = 0;
}
__global__ void count_deg_k(const int* __restrict__ dst, int E) {
    int i = blockIdx.x * blockDim.x + threadIdx.x;
    if (i < E) atomicAdd(&g_deg[dst[i]], 1);
}
__global__ void exscan_k(int n) {
    __shared__ int buf[1024];
    int base = 0;
    for (int start = 0; start < n; start += 1024) {
        int i = start + (int)threadIdx.x;
        int v = (i < n) ? g_deg[i] : 0;
        __syncthreads();
        buf[threadIdx.x] = v;
        __syncthreads();
        #pragma unroll
        for (int off = 1; off < 1024; off <<= 1) {
            int t = (threadIdx.x >= (unsigned)off) ? buf[threadIdx.x - off] : 0;
            __syncthreads();
            buf[threadIdx.x] += t;
            __syncthreads();
        }
        int incl  = buf[threadIdx.x];
        int total = buf[1023];
        if (i < n) {
            int ex = base + incl - v;
            g_off[i] = ex;
            g_cur[i] = ex;
        }
        base += total;
    }
}
__global__ void scatter_k(const int* __restrict__ src, const int* __restrict__ dst, int E) {
    int i = blockIdx.x * blockDim.x + threadIdx.x;
    if (i < E) {
        int p = atomicAdd(&g_cur[dst[i]], 1);
        g_esrc[p] = src[i];
    }
}

// ---------------- segment mean (one block per dst node) ----------------
template <int F>
__global__ void aggregate_k(const float* __restrict__ feat, float* __restrict__ out) {
    int v = blockIdx.x;
    int t = threadIdx.x;
    int o = g_off[v];
    int d = g_deg[v];
    float4 acc = make_float4(0.f, 0.f, 0.f, 0.f);
    for (int j = 0; j < d; j++) {
        int s = g_esrc[o + j];
        float4 x = *reinterpret_cast<const float4*>(&feat[(size_t)s * F + t * 4]);
        acc.x += x.x; acc.y += x.y; acc.z += x.z; acc.w += x.w;
    }
    float inv = 1.0f / (float)max(d, 1);
    acc.x *= inv; acc.y *= inv; acc.z *= inv; acc.w *= inv;
    *reinterpret_cast<float4*>(&out[(size_t)v * F + t * 4]) = acc;
}

// ---------------- weight transpose + tf32 round: W[K,N] -> Wt[N,K] ----------------
__global__ void transpose_cvt_k(const float* __restrict__ W, float* __restrict__ Wt,
                                int K, int N) {
    __shared__ float tile[32][33];
    int n0 = blockIdx.x * 32, k0 = blockIdx.y * 32;
    tile[threadIdx.y][threadIdx.x] = W[(size_t)(k0 + threadIdx.y) * N + n0 + threadIdx.x];
    __syncthreads();
    Wt[(size_t)(n0 + threadIdx.y) * K + k0 + threadIdx.x] = to_tf32(tile[threadIdx.x][threadIdx.y]);
}

// ---------------- TF32 mma.sync dual GEMM ----------------
// C[M,N] = act(A1@W1 + A2@W2 + bias); A fp32 row-major [M,K], B tf32 [N,K] K-major.
// 128x128 CTA tile, BK=32, 256 threads (8 warps, 2x4), 2-stage cp.async pipeline.
// Requires M%128==0, N%128==0, K%32==0.
static constexpr int GSTRIDE = 36;                 // padded floats per 32-col row
static constexpr int ATILE   = 128 * GSTRIDE;      // 4608 floats
static constexpr int STAGE   = 2 * ATILE;          // A + B per stage
static constexpr int SM_BYTES = 2 * STAGE * 4;     // 73728 bytes

template <bool RELU>
__global__ __launch_bounds__(256)
void gemm_mma_k(const float* __restrict__ A1, const float* __restrict__ A2,
                const float* __restrict__ B1t, const float* __restrict__ B2t,
                const float* __restrict__ bias, float* __restrict__ C,
                int M, int N, int K) {
    extern __shared__ float smf[];
    const uint32_t sbase = smem_to_u32(smf);
    const int tid  = threadIdx.x;
    const int wid  = tid >> 5;
    const int lane = tid & 31;
    const int wm   = wid >> 2;        // 0..1
    const int wn   = wid & 3;         // 0..3
    const int g    = lane >> 2;       // 0..7
    const int tig  = lane & 3;        // 0..3
    const int bm   = blockIdx.y * 128;
    const int bn   = blockIdx.x * 128;

    const int ldrow = tid >> 3;       // 0..31 base row (x4 iters)
    const int ldseg = tid & 7;        // 16B segment

    float acc[4][4][4];
    #pragma unroll
    for (int mt = 0; mt < 4; mt++)
        #pragma unroll
        for (int nt = 0; nt < 4; nt++)
            #pragma unroll
            for (int i = 0; i < 4; i++) acc[mt][nt][i] = 0.f;

    const int kt = K / 32;
    const int T  = 2 * kt;

    auto issue_load = [&](int t, int s) {
        int pass = t >= kt;
        int k0 = (t - pass * kt) * 32;
        const float* __restrict__ A = pass ? A2 : A1;
        const float* __restrict__ B = pass ? B2t : B1t;
        uint32_t abase = sbase + (uint32_t)(s * STAGE) * 4;
        uint32_t bbase = abase + (uint32_t)ATILE * 4;
        #pragma unroll
        for (int i = 0; i < 4; i++) {
            int row = ldrow + i * 32;
            uint32_t off = (uint32_t)(row * GSTRIDE + ldseg * 4) * 4;
            cp_async16(abase + off, &A[(size_t)(bm + row) * K + k0 + ldseg * 4]);
            cp_async16(bbase + off, &B[(size_t)(bn + row) * K + k0 + ldseg * 4]);
        }
        cp_commit();
    };

    issue_load(0, 0);

    for (int t = 0; t < T; t++) {
        int s = t & 1;
        if (t + 1 < T) { issue_load(t + 1, s ^ 1); cp_wait<1>(); }
        else           { cp_wait<0>(); }
        __syncthreads();

        // round A slice (the elements this thread loaded) to tf32, in place
        float* As = smf + s * STAGE;
        #pragma unroll
        for (int i = 0; i < 4; i++) {
            float4* p = reinterpret_cast<float4*>(As + (ldrow + i * 32) * GSTRIDE + ldseg * 4);
            float4 v = *p;
            v.x = to_tf32(v.x); v.y = to_tf32(v.y); v.z = to_tf32(v.z); v.w = to_tf32(v.w);
            *p = v;
        }
        __syncthreads();

        const float* Bs = As + ATILE;
        #pragma unroll
        for (int kc = 0; kc < 32; kc += 8) {
            uint32_t a[4][4], b[4][2];
            #pragma unroll
            for (int mt = 0; mt < 4; mt++) {
                int rb = wm * 64 + mt * 16 + g;
                a[mt][0] = __float_as_uint(As[(rb    ) * GSTRIDE + kc + tig    ]);
                a[mt][1] = __float_as_uint(As[(rb + 8) * GSTRIDE + kc + tig    ]);
                a[mt][2] = __float_as_uint(As[(rb    ) * GSTRIDE + kc + tig + 4]);
                a[mt][3] = __float_as_uint(As[(rb + 8) * GSTRIDE + kc + tig + 4]);
            }
            #pragma unroll
            for (int nt = 0; nt < 4; nt++) {
                int nb = wn * 32 + nt * 8 + g;
                b[nt][0] = __float_as_uint(Bs[nb * GSTRIDE + kc + tig    ]);
                b[nt][1] = __float_as_uint(Bs[nb * GSTRIDE + kc + tig + 4]);
            }
            #pragma unroll
            for (int mt = 0; mt < 4; mt++)
                #pragma unroll
                for (int nt = 0; nt < 4; nt++)
                    mma_tf32(acc[mt][nt], a[mt], b[nt]);
        }
        __syncthreads();   // all reads of stage s done before it is overwritten
    }

    // epilogue
    #pragma unroll
    for (int mt = 0; mt < 4; mt++) {
        int r0 = bm + wm * 64 + mt * 16 + g;
        #pragma unroll
        for (int nt = 0; nt < 4; nt++) {
            int c = bn + wn * 32 + nt * 8 + 2 * tig;
            float bx = __ldg(&bias[c]), by = __ldg(&bias[c + 1]);
            float2 v0 = make_float2(acc[mt][nt][0] + bx, acc[mt][nt][1] + by);
            float2 v1 = make_float2(acc[mt][nt][2] + bx, acc[mt][nt][3] + by);
            if (RELU) {
                v0.x = fmaxf(v0.x, 0.f); v0.y = fmaxf(v0.y, 0.f);
                v1.x = fmaxf(v1.x, 0.f); v1.y = fmaxf(v1.y, 0.f);
            }
            *reinterpret_cast<float2*>(&C[(size_t)r0 * N + c]) = v0;
            *reinterpret_cast<float2*>(&C[(size_t)(r0 + 8) * N + c]) = v1;
        }
    }
}

// ---------------- small final GEMM (N=47): one block per output row ----------------
__global__ void gemm_small_k(const float* __restrict__ A1, const float* __restrict__ A2,
                             const float* __restrict__ B1, const float* __restrict__ B2,
                             const float* __restrict__ bias, float* __restrict__ C,
                             int K, int N) {
    __shared__ float a1[HH];
    __shared__ float a2[HH];
    int m = blockIdx.x;
    for (int i = threadIdx.x; i < K; i += blockDim.x) {
        a1[i] = A1[(size_t)m * K + i];
        a2[i] = A2[(size_t)m * K + i];
    }
    __syncthreads();
    for (int c = threadIdx.x; c < N; c += blockDim.x) {
        float s = bias[c];
        #pragma unroll 8
        for (int k = 0; k < K; k++)
            s += a1[k] * B1[(size_t)k * N + c] + a2[k] * B2[(size_t)k * N + c];
        C[(size_t)m * N + c] = s;
    }
}

// ---------------- launch ----------------
extern "C" void kernel_launch(void* const* d_in, const int* in_sizes, int n_in,
                              void* d_out, int out_size) {
    const float* x   = (const float*)d_in[0];
    const int* src0  = (const int*)d_in[1];
    const int* dst0  = (const int*)d_in[2];
    const int* src1  = (const int*)d_in[3];
    const int* dst1  = (const int*)d_in[4];
    const int* src2  = (const int*)d_in[5];
    const int* dst2  = (const int*)d_in[6];
    const float* Ws0 = (const float*)d_in[7];
    const float* Wn0 = (const float*)d_in[8];
    const float* b0  = (const float*)d_in[9];
    const float* Ws1 = (const float*)d_in[10];
    const float* Wn1 = (const float*)d_in[11];
    const float* b1  = (const float*)d_in[12];
    const float* Ws2 = (const float*)d_in[13];
    const float* Wn2 = (const float*)d_in[14];
    const float* b2  = (const float*)d_in[15];
    float* out = (float*)d_out;

    float *mean_p, *h1_p, *h2_p, *w0t_p, *w1t_p;
    cudaGetSymbolAddress((void**)&mean_p, g_mean);
    cudaGetSymbolAddress((void**)&h1_p, g_h1);
    cudaGetSymbolAddress((void**)&h2_p, g_h2);
    cudaGetSymbolAddress((void**)&w0t_p, g_W0t);
    cudaGetSymbolAddress((void**)&w1t_p, g_W1t);

    static int smem_set = 0;
    if (!smem_set) {
        cudaFuncSetAttribute(gemm_mma_k<true>,
                             cudaFuncAttributeMaxDynamicSharedMemorySize, SM_BYTES);
        cudaFuncSetAttribute(gemm_mma_k<false>,
                             cudaFuncAttributeMaxDynamicSharedMemorySize, SM_BYTES);
        smem_set = 1;
    }

    // ---- weight transpose + tf32 round ----
    {
        dim3 blk(32, 32);
        transpose_cvt_k<<<dim3(HH / 32, FF0 / 32), blk>>>(Ws0, w0t_p, FF0, HH);
        transpose_cvt_k<<<dim3(HH / 32, FF0 / 32), blk>>>(Wn0, w0t_p + HH * FF0, FF0, HH);
        transpose_cvt_k<<<dim3(HH / 32, HH / 32), blk>>>(Ws1, w1t_p, HH, HH);
        transpose_cvt_k<<<dim3(HH / 32, HH / 32), blk>>>(Wn1, w1t_p + HH * HH, HH, HH);
    }

    // ---- Layer 0: x[N0,256] -> h1[N1,1024], ReLU ----
    zero_deg_k<<<(NN1 + 255) / 256, 256>>>(NN1);
    count_deg_k<<<(EE0 + 255) / 256, 256>>>(dst0, EE0);
    exscan_k<<<1, 1024>>>(NN1);
    scatter_k<<<(EE0 + 255) / 256, 256>>>(src0, dst0, EE0);
    aggregate_k<FF0><<<NN1, FF0 / 4>>>(x, mean_p);
    gemm_mma_k<true><<<dim3(HH / 128, NN1 / 128), 256, SM_BYTES>>>(
        x, mean_p, w0t_p, w0t_p + HH * FF0, b0, h1_p, NN1, HH, FF0);

    // ---- Layer 1: h1[N1,1024] -> h2[N2,1024], ReLU ----
    zero_deg_k<<<(NN2 + 255) / 256, 256>>>(NN2);
    count_deg_k<<<(EE1 + 255) / 256, 256>>>(dst1, EE1);
    exscan_k<<<1, 1024>>>(NN2);
    scatter_k<<<(EE1 + 255) / 256, 256>>>(src1, dst1, EE1);
    aggregate_k<HH><<<NN2, HH / 4>>>(h1_p, mean_p);
    gemm_mma_k<true><<<dim3(HH / 128, NN2 / 128), 256, SM_BYTES>>>(
        h1_p, mean_p, w1t_p, w1t_p + HH * HH, b1, h2_p, NN2, HH, HH);

    // ---- Layer 2: h2[N2,1024] -> out[N3,47], no activation ----
    zero_deg_k<<<(NN3 + 255) / 256, 256>>>(NN3);
    count_deg_k<<<(EE2 + 255) / 256, 256>>>(dst2, EE2);
    exscan_k<<<1, 1024>>>(NN3);
    scatter_k<<<(EE2 + 255) / 256, 256>>>(src2, dst2, EE2);
    aggregate_k<HH><<<NN3, HH / 4>>>(h2_p, mean_p);
    gemm_small_k<<<NN3, 128>>>(h2_p, mean_p, Ws2, Wn2, b2, out, HH, CC);
}